// round 1
// baseline (speedup 1.0000x reference)
#include <cuda_runtime.h>
#include <cstdint>

// Problem constants
#define NFACES 1000
#define IMG    256
#define SPLIT  8
#define CHUNK  (NFACES / SPLIT)   // 125
#define EPSF   1e-6f
#define KEEP_T 30.0f              // log2-units: sigmoid < 2^-30 < 2^-25 -> (1-frag)==1.0f exactly

// Preprocessed per-face edge coefficients (sign & 100*log2e folded in):
//   L'_e(p) = A_e * px + B_e * py + C_e  ==  -x_e * log2(e), x_e = sdist*s*inv_sigma
//   sigmoid(x_e) = 1 / (1 + 2^{L'_e})
__device__ float4 g_fA[NFACES];   // (A0, B0, C0, A1)
__device__ float4 g_fB[NFACES];   // (B1, C1, A2, B2)
__device__ float  g_fC[NFACES];   // C2
__device__ float  g_part[SPLIT * IMG * IMG];  // per-chunk partial products (2 MB)
__device__ float  g_row[IMG];                 // per-block partial loss sums

__device__ __forceinline__ float ex2f(float x) {
    float y; asm("ex2.approx.f32 %0, %1;" : "=f"(y) : "f"(x)); return y;
}
__device__ __forceinline__ float rcpaf(float x) {
    float y; asm("rcp.approx.f32 %0, %1;" : "=f"(y) : "f"(x)); return y;
}

// ---------------------------------------------------------------------------
// Kernel 1: per-face preprocessing (look_at, projection, edge coefficients)
// ---------------------------------------------------------------------------
__global__ void __launch_bounds__(256) prep_kernel(
    const float* __restrict__ verts,   // (1, V, 3)
    const int*   __restrict__ faces,   // (1, F, 3)
    const float* __restrict__ cam)     // (3,)
{
    int f = blockIdx.x * blockDim.x + threadIdx.x;
    if (f >= NFACES) return;

    float ex = cam[0], ey = cam[1], ez = cam[2];

    // z = normalize(at - eye), at = 0
    float zx = -ex, zy = -ey, zz = -ez;
    float zn = sqrtf(zx*zx + zy*zy + zz*zz) + EPSF;
    zx /= zn; zy /= zn; zz /= zn;
    // x = normalize(cross(up, z)), up = (0,1,0) -> (z2, 0, -z0)
    float xx = zz, xz = -zx;
    float xn = sqrtf(xx*xx + xz*xz) + EPSF;
    xx /= xn; xz /= xn;
    // y = cross(z, x) (x.y == 0)
    float yx = zy * xz;
    float yy = zz * xx - zx * xz;
    float yz = -zy * xx;

    const float w = 0.57735026918962576f;  // tan(30 deg)

    float px[3], py[3];
    #pragma unroll
    for (int k = 0; k < 3; k++) {
        int vi = faces[3 * f + k];
        float dx = verts[3 * vi + 0] - ex;
        float dy = verts[3 * vi + 1] - ey;
        float dz = verts[3 * vi + 2] - ez;
        float cx = xx * dx + xz * dz;          // x.y == 0
        float cy = yx * dx + yy * dy + yz * dz;
        float cz = zx * dx + zy * dy + zz * dz;
        float zw = cz * w;
        px[k] = cx / zw;
        py[k] = cy / zw;
    }

    // area sign (no FMA contraction: match reference near exact zero)
    float e01x = px[1] - px[0], e01y = py[1] - py[0];
    float e02x = px[2] - px[0], e02y = py[2] - py[0];
    float area = __fmul_rn(e01x, e02y) - __fmul_rn(e01y, e02x);
    float s = (area > 0.f) ? 1.f : ((area < 0.f) ? -1.f : 0.f);

    // K = s * inv_sigma * log2(e); degenerate faces (s=0) -> all coeffs 0 ->
    // L'=0 -> frag = 0.125 uniformly (matches sigmoid(0)^3), never culled.
    float K = s * 144.26950408889634f;  // 100 * log2(e)

    float A[3], B[3], C[3];
    const int ia[3] = {0, 1, 2}, ib[3] = {1, 2, 0};
    #pragma unroll
    for (int e = 0; e < 3; e++) {
        float ax = px[ib[e]] - px[ia[e]];
        float ay = py[ib[e]] - py[ia[e]];
        float len = sqrtf(ax*ax + ay*ay) + EPSF;
        float nx = -ay / len, ny = ax / len;
        A[e] = -K * nx;
        B[e] = -K * ny;
        C[e] =  K * (px[ia[e]] * nx + py[ia[e]] * ny);
    }
    g_fA[f] = make_float4(A[0], B[0], C[0], A[1]);
    g_fB[f] = make_float4(B[1], C[1], A[2], B[2]);
    g_fC[f] = C[2];
}

// ---------------------------------------------------------------------------
// Kernel 2: per-(16x16 tile, face-chunk) partial soft-OR product.
// Tile-level conservative culling via interval arithmetic on L'.
// ---------------------------------------------------------------------------
__global__ void __launch_bounds__(256) render_kernel()
{
    __shared__ float4 sA[CHUNK], sB[CHUNK];
    __shared__ float  sC[CHUNK];
    __shared__ int    wcnt[4];

    int tid  = threadIdx.x;
    int lane = tid & 31, wid = tid >> 5;
    int c0 = blockIdx.x * 16, r0 = blockIdx.y * 16;

    // tile pixel-center bounds (y decreases with row)
    float xmin = (2.f * c0 + 1.f)        * (1.f / 256.f) - 1.f;
    float xmax = (2.f * (c0 + 15) + 1.f) * (1.f / 256.f) - 1.f;
    float ymax = 1.f - (2.f * r0 + 1.f)        * (1.f / 256.f);
    float ymin = 1.f - (2.f * (r0 + 15) + 1.f) * (1.f / 256.f);

    int base = blockIdx.z * CHUNK;

    // --- cull: keep face iff some pixel in tile might have all edges "soft" ---
    bool keep = false;
    float4 fa = make_float4(0,0,0,0), fb = make_float4(0,0,0,0);
    float fc = 0.f;
    if (tid < CHUNK) {
        fa = g_fA[base + tid];
        fb = g_fB[base + tid];
        fc = g_fC[base + tid];
        // min over tile of L'_e, per edge; cull iff max_e(min_tile L'_e) >= T
        float m0 = (fa.x > 0.f ? fa.x * xmin : fa.x * xmax)
                 + (fa.y > 0.f ? fa.y * ymin : fa.y * ymax) + fa.z;
        float m1 = (fa.w > 0.f ? fa.w * xmin : fa.w * xmax)
                 + (fb.x > 0.f ? fb.x * ymin : fb.x * ymax) + fb.y;
        float m2 = (fb.z > 0.f ? fb.z * xmin : fb.z * xmax)
                 + (fb.w > 0.f ? fb.w * ymin : fb.w * ymax) + fc;
        keep = fmaxf(m0, fmaxf(m1, m2)) < KEEP_T;
    }
    unsigned bal = __ballot_sync(0xffffffffu, keep);
    if (lane == 0 && wid < 4) wcnt[wid] = __popc(bal);
    __syncthreads();

    int cnt = wcnt[0] + wcnt[1] + wcnt[2] + wcnt[3];
    if (keep) {
        int off = __popc(bal & ((1u << lane) - 1u));
        #pragma unroll
        for (int w2 = 0; w2 < 3; w2++) if (w2 < wid) off += wcnt[w2];
        sA[off] = fa; sB[off] = fb; sC[off] = fc;
    }
    __syncthreads();

    int gc = c0 + (tid & 15);
    int gr = r0 + (tid >> 4);
    float X = (2.f * gc + 1.f) * (1.f / 256.f) - 1.f;
    float Y = 1.f - (2.f * gr + 1.f) * (1.f / 256.f);

    float prod = 1.f;
    for (int i = 0; i < cnt; i++) {
        float4 a = sA[i];
        float4 b = sB[i];
        float  cc = sC[i];
        float L0 = fmaf(a.x, X, fmaf(a.y, Y, a.z));
        float L1 = fmaf(a.w, X, fmaf(b.x, Y, b.y));
        float L2 = fmaf(b.z, X, fmaf(b.w, Y, cc));
        // frag = 1/((1+e0)(1+e1)(1+e2)); keep factors >=1 -> no inf*0 NaN
        float u0 = 1.f + ex2f(L0);
        float u1 = 1.f + ex2f(L1);
        float u2 = 1.f + ex2f(L2);
        float P  = u0 * u1 * u2;      // in [1, inf]; inf -> frag 0 -> factor 1
        float r  = rcpaf(P);          // = frag
        prod = fmaf(prod, -r, prod);  // prod *= (1 - frag)
    }
    g_part[blockIdx.z * (IMG * IMG) + gr * IMG + gc] = prod;
}

// ---------------------------------------------------------------------------
// Kernel 3: combine chunk products, per-pixel loss, per-block reduction
// ---------------------------------------------------------------------------
__global__ void __launch_bounds__(256) combine_kernel(const float* __restrict__ ref)
{
    __shared__ float red[256];
    int tid = threadIdx.x;
    int pix = blockIdx.x * 256 + tid;
    float p = 1.f;
    #pragma unroll
    for (int z = 0; z < SPLIT; z++) p *= g_part[z * (IMG * IMG) + pix];
    float sil = 1.f - p;
    float d = sil - ref[pix];
    red[tid] = d * d;
    __syncthreads();
    #pragma unroll
    for (int s2 = 128; s2 > 0; s2 >>= 1) {
        if (tid < s2) red[tid] += red[tid + s2];
        __syncthreads();
    }
    if (tid == 0) g_row[blockIdx.x] = red[0];
}

// ---------------------------------------------------------------------------
// Kernel 4: final deterministic reduction to the scalar loss
// ---------------------------------------------------------------------------
__global__ void __launch_bounds__(256) final_kernel(float* __restrict__ out)
{
    __shared__ float red[256];
    int tid = threadIdx.x;
    red[tid] = g_row[tid];
    __syncthreads();
    #pragma unroll
    for (int s2 = 128; s2 > 0; s2 >>= 1) {
        if (tid < s2) red[tid] += red[tid + s2];
        __syncthreads();
    }
    if (tid == 0) out[0] = red[0];
}

extern "C" void kernel_launch(void* const* d_in, const int* in_sizes, int n_in,
                              void* d_out, int out_size)
{
    const float* verts = (const float*)d_in[0];   // (1,502,3)
    const int*   faces = (const int*)  d_in[1];   // (1,1000,3)
    const float* cam   = (const float*)d_in[2];   // (3,)
    const float* ref   = (const float*)d_in[3];   // (1,256,256)

    prep_kernel<<<(NFACES + 255) / 256, 256>>>(verts, faces, cam);

    dim3 grid(IMG / 16, IMG / 16, SPLIT);
    render_kernel<<<grid, 256>>>();

    combine_kernel<<<(IMG * IMG) / 256, 256>>>(ref);
    final_kernel<<<1, 256>>>((float*)d_out);
}